// round 1
// baseline (speedup 1.0000x reference)
#include <cuda_runtime.h>
#include <cuda_bf16.h>

// Problem constants (shapes fixed by setup_inputs)
#define BATCH 8
#define L 128
#define D 768
#define NROW (BATCH * L * L)        // 131072 rows of length D
#define PER_B (L * L)               // 16384
#define K1_BLOCKS (NROW / 8)        // 8 warps/block, 1 row/warp -> 16384 blocks

// Device scratch (no allocations allowed)
__device__ float g_predS[NROW];
__device__ float g_predE[NROW];
__device__ float g_partS[K1_BLOCKS];
__device__ float g_partE[K1_BLOCKS];
__device__ float g_thrS[BATCH];
__device__ float g_thrE[BATCH];

// ---------------------------------------------------------------------------
// K1: fused dual dot-product + BCE partials + sigmoid preds.
// One warp per row (768 floats = 192 float4; 6 float4 per lane).
// ---------------------------------------------------------------------------
__global__ __launch_bounds__(256) void k_main(
    const float* __restrict__ table,
    const float* __restrict__ W_S, const float* __restrict__ b_S,
    const float* __restrict__ W_E, const float* __restrict__ b_E,
    const int* __restrict__ labS, const int* __restrict__ labE)
{
    __shared__ float sWs[D];
    __shared__ float sWe[D];
    __shared__ float warpS[8];
    __shared__ float warpE[8];

    for (int i = threadIdx.x; i < D; i += 256) {
        sWs[i] = W_S[i];
        sWe[i] = W_E[i];
    }
    __syncthreads();

    const int warp = threadIdx.x >> 5;
    const int lane = threadIdx.x & 31;
    const long long row = (long long)blockIdx.x * 8 + warp;

    const float4* __restrict__ t  = (const float4*)(table + row * D);
    const float4* __restrict__ ws = (const float4*)sWs;
    const float4* __restrict__ we = (const float4*)sWe;

    float sS = 0.f, sE = 0.f;
#pragma unroll
    for (int j = 0; j < 6; j++) {
        const int idx = lane + 32 * j;
        float4 v = t[idx];
        float4 a = ws[idx];
        float4 b = we[idx];
        sS += v.x * a.x + v.y * a.y + v.z * a.z + v.w * a.w;
        sE += v.x * b.x + v.y * b.y + v.z * b.z + v.w * b.w;
    }
#pragma unroll
    for (int o = 16; o; o >>= 1) {
        sS += __shfl_xor_sync(0xFFFFFFFFu, sS, o);
        sE += __shfl_xor_sync(0xFFFFFFFFu, sE, o);
    }

    if (lane == 0) {
        const float lS = sS + b_S[0];
        const float lE = sE + b_E[0];
        const int tS = labS[row];
        const int tE = labE[row];
        const float w = (tS >= 0) ? 1.0f : 0.0f;
        // stable BCE-with-logits: max(x,0) - x*t + log1p(exp(-|x|))
        const float bceS = fmaxf(lS, 0.f) - lS * (float)tS + log1pf(expf(-fabsf(lS)));
        const float bceE = fmaxf(lE, 0.f) - lE * (float)tE + log1pf(expf(-fabsf(lE)));
        warpS[warp] = w * bceS;
        warpE[warp] = w * bceE;
        g_predS[row] = w / (1.0f + expf(-lS));
        g_predE[row] = w / (1.0f + expf(-lE));
    }
    __syncthreads();

    if (threadIdx.x == 0) {
        float a = 0.f, b = 0.f;
#pragma unroll
        for (int i = 0; i < 8; i++) { a += warpS[i]; b += warpE[i]; }
        g_partS[blockIdx.x] = a;
        g_partE[blockIdx.x] = b;
    }
}

// ---------------------------------------------------------------------------
// K2: deterministic fixed-order reduction of loss partials -> out[0], out[1]
// ---------------------------------------------------------------------------
__global__ __launch_bounds__(256) void k_reduce(float* __restrict__ out)
{
    __shared__ float sA[256];
    __shared__ float sB[256];
    float a = 0.f, b = 0.f;
    for (int i = threadIdx.x; i < K1_BLOCKS; i += 256) {
        a += g_partS[i];
        b += g_partE[i];
    }
    sA[threadIdx.x] = a;
    sB[threadIdx.x] = b;
    __syncthreads();
    for (int s = 128; s; s >>= 1) {
        if (threadIdx.x < s) {
            sA[threadIdx.x] += sA[threadIdx.x + s];
            sB[threadIdx.x] += sB[threadIdx.x + s];
        }
        __syncthreads();
    }
    if (threadIdx.x == 0) {
        out[0] = sA[0] / (float)NROW;
        out[1] = sB[0] / (float)NROW;
    }
}

// ---------------------------------------------------------------------------
// K3: per-(batch, head) k-th largest via 4-pass radix select on
// order-preserving uint keys. Bit-exact threshold so `pred >= thr`
// reproduces the reference's sort + take_along_axis semantics.
// blockIdx.x in [0,16): [0,8) -> S head, [8,16) -> E head.
// ---------------------------------------------------------------------------
__device__ __forceinline__ unsigned enc_f32(float f)
{
    unsigned u = __float_as_uint(f);
    return (u & 0x80000000u) ? ~u : (u | 0x80000000u);
}

__global__ __launch_bounds__(256) void k_select(const int* __restrict__ mask)
{
    const int b = blockIdx.x & 7;
    const bool isS = blockIdx.x < 8;
    const float* __restrict__ pred = (isS ? g_predS : g_predE) + b * PER_B;

    __shared__ unsigned hist[256];
    __shared__ unsigned s_prefix;
    __shared__ unsigned s_pmask;
    __shared__ int s_k;

    if (threadIdx.x == 0) {
        int msum = 0;
        for (int i = 0; i < L; i++) msum += mask[b * L + i];
        const int mlen = msum - 2;
        int len = (int)((float)mlen * 0.3f);   // trunc, same as .astype(int32)
        if (len < 5) len = 5;
        const int mlsq = mlen * mlen;
        if (len > mlsq) len = mlsq;
        if (len < 1) len = 1;
        if (len > PER_B) len = PER_B;
        s_k = len;
        s_prefix = 0u;
        s_pmask = 0u;
    }
    __syncthreads();

    for (int pass = 3; pass >= 0; pass--) {
        const int shift = pass * 8;
        for (int i = threadIdx.x; i < 256; i += 256) hist[i] = 0u;
        __syncthreads();
        const unsigned pm = s_pmask;
        const unsigned pf = s_prefix;
        for (int i = threadIdx.x; i < PER_B; i += 256) {
            const unsigned key = enc_f32(pred[i]);
            if ((key & pm) == pf) atomicAdd(&hist[(key >> shift) & 0xFFu], 1u);
        }
        __syncthreads();
        if (threadIdx.x == 0) {
            const unsigned kk = (unsigned)s_k;
            unsigned cum = 0;
            int c = 255;
            for (; c > 0; c--) {
                if (cum + hist[c] >= kk) break;
                cum += hist[c];
            }
            s_k = (int)(kk - cum);
            s_prefix = pf | ((unsigned)c << shift);
            s_pmask = pm | (0xFFu << shift);
        }
        __syncthreads();
    }

    if (threadIdx.x == 0) {
        const unsigned u = s_prefix;
        const float thr = (u & 0x80000000u) ? __uint_as_float(u & 0x7FFFFFFFu)
                                            : __uint_as_float(~u);
        if (isS) g_thrS[b] = thr; else g_thrE[b] = thr;
    }
}

// ---------------------------------------------------------------------------
// K4: write predict masks as 0.0/1.0 floats
// out layout: [loss_S, loss_E, predict_S(131072), predict_E(131072)]
// ---------------------------------------------------------------------------
__global__ __launch_bounds__(256) void k_predict(float* __restrict__ out)
{
    const int i = blockIdx.x * 256 + threadIdx.x;
    if (i < NROW) {
        const int b = i >> 14;  // / PER_B
        out[2 + i] = (g_predS[i] >= g_thrS[b]) ? 1.0f : 0.0f;
    } else {
        const int j = i - NROW;
        const int b = j >> 14;
        out[2 + NROW + j] = (g_predE[j] >= g_thrE[b]) ? 1.0f : 0.0f;
    }
}

// ---------------------------------------------------------------------------
extern "C" void kernel_launch(void* const* d_in, const int* in_sizes, int n_in,
                              void* d_out, int out_size)
{
    // metadata order: table, attention_mask, table_labels_S, table_labels_E,
    //                 W_S, b_S, W_E, b_E
    const float* table = (const float*)d_in[0];
    const int*   amask = (const int*)d_in[1];
    const int*   labS  = (const int*)d_in[2];
    const int*   labE  = (const int*)d_in[3];
    const float* W_S   = (const float*)d_in[4];
    const float* b_S   = (const float*)d_in[5];
    const float* W_E   = (const float*)d_in[6];
    const float* b_E   = (const float*)d_in[7];
    float* out = (float*)d_out;

    k_main<<<K1_BLOCKS, 256>>>(table, W_S, b_S, W_E, b_E, labS, labE);
    k_reduce<<<1, 256>>>(out);
    k_select<<<16, 256>>>(amask);
    k_predict<<<(2 * NROW) / 256, 256>>>(out);
}